// round 5
// baseline (speedup 1.0000x reference)
#include <cuda_runtime.h>
#include <cuda_bf16.h>
#include <math.h>

#define MAXN 100000
#define MAXE 3200000

// ---------------- scratch (static device globals; no allocation) -------------
__device__ __nv_bfloat16 g_hs1[(size_t)MAXN * 128]; // (X@W1)*dinv, bf16 payload
__device__ float g_h1 [(size_t)MAXN * 128];         // h1 (fp32); reused as a1
__device__ __nv_bfloat16 g_h2s[(size_t)MAXN * 64];  // (h1@W2)*dinv, bf16 payload
__device__ float g_h2 [(size_t)MAXN * 64];          // h2 (fp32)
__device__ float g_s  [(size_t)MAXN * 8];           // exp(attention logits)
__device__ float g_dinv[MAXN];
__device__ int   g_cnt [MAXN];
__device__ int   g_tmp [MAXN];
__device__ int   g_off [MAXN + 1];
__device__ int   g_cur [MAXN];
__device__ int   g_ecsr[MAXE];
__device__ int   g_bsum[128];
__device__ int   g_bpre[128];
__device__ float g_Z[8];
__device__ float g_G[512];
__device__ float g_C[64];

// ---------------- init / degree / CSR build ----------------------------------
__global__ void k_init(int n) {
    int i = blockIdx.x * blockDim.x + threadIdx.x;
    if (i < n)   g_cnt[i] = 0;
    if (i < 512) g_G[i] = 0.0f;
    if (i < 64)  g_C[i] = 0.0f;
    if (i < 8)   g_Z[i] = 0.0f;
}

__global__ void k_deg(const int* __restrict__ dst, int e) {
    int i = blockIdx.x * blockDim.x + threadIdx.x;
    if (i < e) atomicAdd(&g_cnt[dst[i]], 1);
}

__global__ void k_dinv(int n) {
    int i = blockIdx.x * blockDim.x + threadIdx.x;
    if (i < n) g_dinv[i] = rsqrtf((float)(g_cnt[i] + 1)); // +1 self loop
}

__global__ void k_scan1(int n) {
    __shared__ int sh[1024];
    int i = blockIdx.x * 1024 + threadIdx.x;
    int v = (i < n) ? g_cnt[i] : 0;
    sh[threadIdx.x] = v;
    __syncthreads();
#pragma unroll
    for (int off = 1; off < 1024; off <<= 1) {
        int t = (threadIdx.x >= off) ? sh[threadIdx.x - off] : 0;
        __syncthreads();
        sh[threadIdx.x] += t;
        __syncthreads();
    }
    if (i < n) g_tmp[i] = sh[threadIdx.x];
    if (threadIdx.x == 1023) g_bsum[blockIdx.x] = sh[1023];
}

__global__ void k_scan2(int nb) { // one block, 128 threads
    int t = threadIdx.x;
    int orig = (t < nb) ? g_bsum[t] : 0;
    int v = orig;
#pragma unroll
    for (int off = 1; off < 32; off <<= 1) {
        int u = __shfl_up_sync(0xFFFFFFFF, v, off);
        if ((t & 31) >= off) v += u;
    }
    __shared__ int ws[4];
    if ((t & 31) == 31) ws[t >> 5] = v;
    __syncthreads();
    int add = 0;
    for (int w = 0; w < (t >> 5); w++) add += ws[w];
    v += add;
    if (t < nb) g_bpre[t] = v - orig; // exclusive
}

__global__ void k_scan3(int n) {
    int i = blockIdx.x * 1024 + threadIdx.x;
    if (i < n) {
        int inc = g_tmp[i] + g_bpre[blockIdx.x];
        g_off[i + 1] = inc;
        g_cur[i]     = inc - g_cnt[i];
    }
    if (i == 0) g_off[0] = 0;
}

__global__ void k_bucket(const int* __restrict__ src, const int* __restrict__ dst, int e) {
    int i = blockIdx.x * blockDim.x + threadIdx.x;
    if (i < e) {
        int d   = dst[i];
        int pos = atomicAdd(&g_cur[d], 1);
        g_ecsr[pos] = src[i];
    }
}

// ---------------- 4x4 register-tiled fp32 GEMM (R2-proven) --------------------
// MODE 0: out_bf16[i,:] = (A[i,:]@W) * dinv[i]      (bf16 payload store)
// MODE 1: out_f32[i,:]  = tanh(A[i,:]@W + bias)
template <int K, int C, int MODE>
__global__ void gemm_kernel(const float* __restrict__ A,
                            const float* __restrict__ W,
                            const float* __restrict__ bias,
                            __nv_bfloat16* __restrict__ outb,
                            float* __restrict__ outf,
                            int n) {
    constexpr int BM  = 128;
    constexpr int TN  = 4;
    constexpr int NCG = C / TN;
    constexpr int NRG = 256 / NCG;
    constexpr int TM  = BM / NRG;
    constexpr int KC  = 32;

    __shared__ float Ash[BM * KC];
    __shared__ float Bsh[KC * C];

    int tid = threadIdx.x;
    int m0  = blockIdx.x * BM;
    int tc  = tid % NCG;
    int tr  = tid / NCG;

    float acc[TM][TN];
#pragma unroll
    for (int i = 0; i < TM; i++)
#pragma unroll
        for (int j = 0; j < TN; j++) acc[i][j] = 0.0f;

    for (int kc = 0; kc < K; kc += KC) {
        constexpr int AF4 = BM * KC / 4;
#pragma unroll
        for (int t = tid; t < AF4; t += 256) {
            int r  = t / (KC / 4);
            int c4 = t % (KC / 4);
            float4 v = make_float4(0.f, 0.f, 0.f, 0.f);
            int row = m0 + r;
            if (row < n)
                v = *reinterpret_cast<const float4*>(&A[(size_t)row * K + kc + c4 * 4]);
            *reinterpret_cast<float4*>(&Ash[r * KC + c4 * 4]) = v;
        }
        constexpr int BF4 = KC * C / 4;
#pragma unroll
        for (int t = tid; t < BF4; t += 256) {
            int r  = t / (C / 4);
            int c4 = t % (C / 4);
            *reinterpret_cast<float4*>(&Bsh[r * C + c4 * 4]) =
                *reinterpret_cast<const float4*>(&W[(size_t)(kc + r) * C + c4 * 4]);
        }
        __syncthreads();
#pragma unroll
        for (int k4 = 0; k4 < KC / 4; k4++) {
            float4 b0 = *reinterpret_cast<const float4*>(&Bsh[(k4 * 4 + 0) * C + tc * TN]);
            float4 b1 = *reinterpret_cast<const float4*>(&Bsh[(k4 * 4 + 1) * C + tc * TN]);
            float4 b2 = *reinterpret_cast<const float4*>(&Bsh[(k4 * 4 + 2) * C + tc * TN]);
            float4 b3 = *reinterpret_cast<const float4*>(&Bsh[(k4 * 4 + 3) * C + tc * TN]);
#pragma unroll
            for (int i = 0; i < TM; i++) {
                float4 a = *reinterpret_cast<const float4*>(&Ash[(tr * TM + i) * KC + k4 * 4]);
                acc[i][0] += a.x * b0.x + a.y * b1.x + a.z * b2.x + a.w * b3.x;
                acc[i][1] += a.x * b0.y + a.y * b1.y + a.z * b2.y + a.w * b3.y;
                acc[i][2] += a.x * b0.z + a.y * b1.z + a.z * b2.z + a.w * b3.z;
                acc[i][3] += a.x * b0.w + a.y * b1.w + a.z * b2.w + a.w * b3.w;
            }
        }
        __syncthreads();
    }

#pragma unroll
    for (int i = 0; i < TM; i++) {
        int row = m0 + tr * TM + i;
        if (row >= n) continue;
        if (MODE == 0) {
            float sc = g_dinv[row];
            __nv_bfloat162 lo = __floats2bfloat162_rn(acc[i][0] * sc, acc[i][1] * sc);
            __nv_bfloat162 hi = __floats2bfloat162_rn(acc[i][2] * sc, acc[i][3] * sc);
            uint2 pk = make_uint2(*reinterpret_cast<unsigned*>(&lo),
                                  *reinterpret_cast<unsigned*>(&hi));
            *reinterpret_cast<uint2*>(&outb[(size_t)row * C + tc * TN]) = pk;
        } else {
            float4 o;
            o.x = tanhf(acc[i][0] + bias[tc * TN + 0]);
            o.y = tanhf(acc[i][1] + bias[tc * TN + 1]);
            o.z = tanhf(acc[i][2] + bias[tc * TN + 2]);
            o.w = tanhf(acc[i][3] + bias[tc * TN + 3]);
            *reinterpret_cast<float4*>(&outf[(size_t)row * C + tc * TN]) = o;
        }
    }
}

// ---------------- bf16 helpers -------------------------------------------------
__device__ __forceinline__ float4 bf16x4_to_f4(uint2 p) {
    __nv_bfloat162 lo = *reinterpret_cast<__nv_bfloat162*>(&p.x);
    __nv_bfloat162 hi = *reinterpret_cast<__nv_bfloat162*>(&p.y);
    float2 a = __bfloat1622float2(lo);
    float2 b = __bfloat1622float2(hi);
    return make_float4(a.x, a.y, b.x, b.y);
}

// ---------------- CSR gather aggregation (bf16 payload, prescaled) ------------
// acc = hs[node] + sum hs[s];  h1 = relu(acc*dinv[node] + b1)
__global__ void gather128(const __nv_bfloat16* __restrict__ hs,
                          const float* __restrict__ b1,
                          float* __restrict__ out, int n) {
    int warp = (blockIdx.x * blockDim.x + threadIdx.x) >> 5;
    int lane = threadIdx.x & 31;
    if (warp >= n) return;
    const int node = warp;
    const uint2* base = reinterpret_cast<const uint2*>(hs);
    // row r -> base + r*32 + lane
    float4 acc = bf16x4_to_f4(__ldg(base + (size_t)node * 32 + lane));
    int j = g_off[node], jend = g_off[node + 1];
    for (; j + 2 <= jend; j += 2) {
        int s0 = __ldg(&g_ecsr[j]);
        int s1 = __ldg(&g_ecsr[j + 1]);
        float4 v0 = bf16x4_to_f4(__ldg(base + (size_t)s0 * 32 + lane));
        float4 v1 = bf16x4_to_f4(__ldg(base + (size_t)s1 * 32 + lane));
        acc.x += v0.x + v1.x; acc.y += v0.y + v1.y;
        acc.z += v0.z + v1.z; acc.w += v0.w + v1.w;
    }
    if (j < jend) {
        int s0 = __ldg(&g_ecsr[j]);
        float4 v0 = bf16x4_to_f4(__ldg(base + (size_t)s0 * 32 + lane));
        acc.x += v0.x; acc.y += v0.y; acc.z += v0.z; acc.w += v0.w;
    }
    float dn = g_dinv[node];
    float4 bb = *reinterpret_cast<const float4*>(&b1[lane * 4]);
    float4 o = make_float4(fmaxf(acc.x * dn + bb.x, 0.f), fmaxf(acc.y * dn + bb.y, 0.f),
                           fmaxf(acc.z * dn + bb.z, 0.f), fmaxf(acc.w * dn + bb.w, 0.f));
    *reinterpret_cast<float4*>(&out[(size_t)node * 128 + lane * 4]) = o;
}

__global__ void gather64(const __nv_bfloat16* __restrict__ hs,
                         const float* __restrict__ b2,
                         float* __restrict__ out, int n) {
    int warp = (blockIdx.x * blockDim.x + threadIdx.x) >> 5;
    int lane = threadIdx.x & 31;
    if (warp >= n) return;
    const int node = warp;
    const unsigned* base = reinterpret_cast<const unsigned*>(hs);
    // row r -> base + r*32 + lane  (2 bf16 per lane)
    unsigned p = __ldg(base + (size_t)node * 32 + lane);
    float2 acc = __bfloat1622float2(*reinterpret_cast<__nv_bfloat162*>(&p));
    int j = g_off[node], jend = g_off[node + 1];
    for (; j + 2 <= jend; j += 2) {
        int s0 = __ldg(&g_ecsr[j]);
        int s1 = __ldg(&g_ecsr[j + 1]);
        unsigned p0 = __ldg(base + (size_t)s0 * 32 + lane);
        unsigned p1 = __ldg(base + (size_t)s1 * 32 + lane);
        float2 v0 = __bfloat1622float2(*reinterpret_cast<__nv_bfloat162*>(&p0));
        float2 v1 = __bfloat1622float2(*reinterpret_cast<__nv_bfloat162*>(&p1));
        acc.x += v0.x + v1.x; acc.y += v0.y + v1.y;
    }
    if (j < jend) {
        int s0 = __ldg(&g_ecsr[j]);
        unsigned p0 = __ldg(base + (size_t)s0 * 32 + lane);
        float2 v0 = __bfloat1622float2(*reinterpret_cast<__nv_bfloat162*>(&p0));
        acc.x += v0.x; acc.y += v0.y;
    }
    float dn = g_dinv[node];
    float2 bb = *reinterpret_cast<const float2*>(&b2[lane * 2]);
    float2 o = make_float2(acc.x * dn + bb.x, acc.y * dn + bb.y);
    *reinterpret_cast<float2*>(&out[(size_t)node * 64 + lane * 2]) = o;
}

// ---------------- attention logits -> exp(s), fused Z accumulation ------------
__global__ void k_logits(const float* __restrict__ a1, const float* __restrict__ Wf2,
                         const float* __restrict__ bf2, int n) {
    __shared__ float Wsh[64 * 8];
    __shared__ float bsh[8];
    __shared__ float red[256];
    int tid = threadIdx.x;
    for (int t = tid; t < 512; t += 256) Wsh[t] = Wf2[t];
    if (tid < 8) bsh[tid] = bf2[tid];
    __syncthreads();

    int node = blockIdx.x * 32 + (tid >> 3);
    int d    = tid & 7;
    float e  = 0.0f;
    if (node < n) {
        float acc = bsh[d];
        const float* ar = a1 + (size_t)node * 64;
#pragma unroll 8
        for (int j = 0; j < 64; j++) acc += ar[j] * Wsh[j * 8 + d];
        e = expf(acc);
        g_s[(size_t)node * 8 + d] = e;
    }
    red[tid] = e;
    __syncthreads();
    for (int off = 128; off >= 8; off >>= 1) {
        if (tid < off) red[tid] += red[tid + off];
        __syncthreads();
    }
    if (tid < 8) atomicAdd(&g_Z[tid], red[tid]);
}

// ---------------- pooled reductions: G = e.T@h2, C = e.T@e --------------------
__global__ void k_accum(int n) {
    __shared__ float h2sh[64 * 64];
    __shared__ float esh[64 * 8];
    int tid = threadIdx.x;
    int c0  = blockIdx.x * 64;
    int nv  = n - c0;
    if (nv > 64) nv = 64;

    for (int t = tid; t < 64 * 64; t += 256) {
        int row = t >> 6;
        if (row < nv) h2sh[t] = g_h2[(size_t)(c0 + row) * 64 + (t & 63)];
    }
    for (int t = tid; t < 512; t += 256) {
        int row = t >> 3;
        if (row < nv) esh[t] = g_s[(size_t)(c0 + row) * 8 + (t & 7)];
    }
    __syncthreads();

    int p0 = tid, p1 = tid + 256;
    int d0 = p0 >> 6, h0 = p0 & 63;
    int d1 = p1 >> 6, h1 = p1 & 63;
    int cd1 = tid >> 3, cd2 = tid & 7;
    float aG0 = 0.f, aG1 = 0.f, aC = 0.f;
    for (int m = 0; m < nv; m++) {
        float* hrow = &h2sh[m * 64];
        float* erow = &esh[m * 8];
        aG0 += erow[d0] * hrow[h0];
        aG1 += erow[d1] * hrow[h1];
        if (tid < 64) aC += erow[cd1] * erow[cd2];
    }
    atomicAdd(&g_G[p0], aG0);
    atomicAdd(&g_G[p1], aG1);
    if (tid < 64) atomicAdd(&g_C[tid], aC);
}

// ---------------- final: normalize, penalty, dense head, log_softmax ----------
__global__ void k_final(const float* __restrict__ Wl, const float* __restrict__ bl,
                        float* __restrict__ out) {
    __shared__ float ge[512];
    __shared__ float Zs[8];
    __shared__ float tmp[16];
    __shared__ float lg[10];
    int tid = threadIdx.x; // 64 threads
    if (tid < 8) Zs[tid] = g_Z[tid];
    __syncthreads();
    for (int p = tid; p < 512; p += 64) {
        float v = g_G[p] / Zs[p >> 6];
        ge[p]  = v;
        out[p] = v;
    }
    __syncthreads();
    if (tid < 8) {
        float ss = 0.f;
        for (int d2 = 0; d2 < 8; d2++) {
            float c = g_C[tid * 8 + d2] / (Zs[tid] * Zs[d2]) - (tid == d2 ? 1.0f : 0.0f);
            ss += c * c;
        }
        tmp[tid] = sqrtf(ss);
    }
    __syncthreads();
    if (tid == 0) {
        float pen = 0.f;
        for (int d = 0; d < 8; d++) pen += tmp[d];
        out[512] = pen;
    }
    if (tid < 10) {
        float acc = bl[tid];
        for (int p = 0; p < 512; p++) acc += ge[p] * Wl[p * 10 + tid];
        lg[tid] = acc;
    }
    __syncthreads();
    if (tid == 0) {
        float m = lg[0];
        for (int l = 1; l < 10; l++) m = fmaxf(m, lg[l]);
        float s = 0.f;
        for (int l = 0; l < 10; l++) s += expf(lg[l] - m);
        tmp[0] = m + logf(s);
    }
    __syncthreads();
    if (tid < 10) out[513 + tid] = lg[tid] - tmp[0];
}

// ---------------- launch -------------------------------------------------------
extern "C" void kernel_launch(void* const* d_in, const int* in_sizes, int n_in,
                              void* d_out, int out_size) {
    const int*   edges = (const int*)d_in[0];
    const float* X     = (const float*)d_in[1];
    const float* W1    = (const float*)d_in[2];
    const float* b1    = (const float*)d_in[3];
    const float* W2    = (const float*)d_in[4];
    const float* b2    = (const float*)d_in[5];
    const float* Wf1   = (const float*)d_in[6];
    const float* bf1   = (const float*)d_in[7];
    const float* Wf2   = (const float*)d_in[8];
    const float* bf2   = (const float*)d_in[9];
    const float* Wl    = (const float*)d_in[10];
    const float* bl    = (const float*)d_in[11];
    float* out = (float*)d_out;

    int e = in_sizes[0] / 2;
    int n = in_sizes[1] / 128;
    const int* src = edges;
    const int* dst = edges + e;

    __nv_bfloat16 *pHs1, *pH2s;
    float *pH1, *pH2;
    cudaGetSymbolAddress((void**)&pHs1, g_hs1);
    cudaGetSymbolAddress((void**)&pH1,  g_h1);
    cudaGetSymbolAddress((void**)&pH2s, g_h2s);
    cudaGetSymbolAddress((void**)&pH2,  g_h2);
    float* pA1 = pH1; // reuse h1 buffer for a1 (h1 dead after gemm2)

    static cudaStream_t sCsr = nullptr;
    static cudaEvent_t evDeg = nullptr, evCsr = nullptr;
    if (!sCsr) {
        cudaStreamCreateWithFlags(&sCsr, cudaStreamNonBlocking);
        cudaEventCreateWithFlags(&evDeg, cudaEventDisableTiming);
        cudaEventCreateWithFlags(&evCsr, cudaEventDisableTiming);
    }

    const int T  = 256;
    const int NB = (n + 1023) / 1024;

    // main: degree + dinv (needed by gemm1 epilogue)
    k_init<<<(n + T - 1) / T, T>>>(n);
    k_deg <<<(e + T - 1) / T, T>>>(dst, e);
    k_dinv<<<(n + T - 1) / T, T>>>(n);
    cudaEventRecord(evDeg, 0);

    // side: CSR scan + bucket (overlaps gemm1)
    cudaStreamWaitEvent(sCsr, evDeg, 0);
    k_scan1 <<<NB, 1024, 0, sCsr>>>(n);
    k_scan2 <<<1, 128, 0, sCsr>>>(NB);
    k_scan3 <<<NB, 1024, 0, sCsr>>>(n);
    k_bucket<<<(e + T - 1) / T, T, 0, sCsr>>>(src, dst, e);
    cudaEventRecord(evCsr, sCsr);

    // main: gemm1 -> bf16 scaled payload
    gemm_kernel<128, 128, 0><<<(n + 127) / 128, T>>>(X, W1, nullptr, pHs1, nullptr, n);

    cudaStreamWaitEvent(0, evCsr, 0);
    gather128<<<(n + 7) / 8, T>>>(pHs1, b1, pH1, n);
    gemm_kernel<128, 64, 0><<<(n + 127) / 128, T>>>(pH1, W2, nullptr, pH2s, nullptr, n);
    gather64<<<(n + 7) / 8, T>>>(pH2s, b2, pH2, n);
    gemm_kernel<64, 64, 1><<<(n + 127) / 128, T>>>(pH2, Wf1, bf1, nullptr, pA1, n);
    k_logits<<<(n + 31) / 32, T>>>(pA1, Wf2, bf2, n);
    k_accum <<<(n + 63) / 64, T>>>(n);
    k_final <<<1, 64>>>(Wl, bl, out);
}

// round 6
// speedup vs baseline: 1.1258x; 1.1258x over previous
#include <cuda_runtime.h>
#include <math.h>

#define MAXN 100000
#define MAXE 3200000

// ---------------- scratch (static device globals; no allocation) -------------
__device__ float g_hs1 [(size_t)MAXN * 128]; // (X@W1)*dinv
__device__ float g_h1  [(size_t)MAXN * 128]; // h1; reused as a1 after gemm2
__device__ float g_h2s [(size_t)MAXN * 64];  // (h1@W2)*dinv
__device__ float g_h2  [(size_t)MAXN * 64];  // h2
__device__ float g_s   [(size_t)MAXN * 8];   // exp(attention logits)
__device__ float g_dinv[MAXN];
__device__ int   g_cnt [MAXN];
__device__ int   g_tmp [MAXN];
__device__ int   g_off [MAXN + 1];
__device__ int   g_cur [MAXN];
__device__ int   g_ecsr[MAXE];
__device__ int   g_bsum[128];
__device__ int   g_bpre[128];
__device__ float g_Z[8];
__device__ float g_G[512];
__device__ float g_C[64];

// ---------------- init / degree / CSR build ----------------------------------
__global__ void k_init(int n) {
    int i = blockIdx.x * blockDim.x + threadIdx.x;
    if (i < n)   g_cnt[i] = 0;
    if (i < 512) g_G[i] = 0.0f;
    if (i < 64)  g_C[i] = 0.0f;
    if (i < 8)   g_Z[i] = 0.0f;
}

__global__ void k_deg(const int* __restrict__ dst, int e) {
    int i = blockIdx.x * blockDim.x + threadIdx.x;
    if (i < e) atomicAdd(&g_cnt[dst[i]], 1);
}

__global__ void k_dinv(int n) {
    int i = blockIdx.x * blockDim.x + threadIdx.x;
    if (i < n) g_dinv[i] = rsqrtf((float)(g_cnt[i] + 1)); // +1 self loop
}

__global__ void k_scan1(int n) {
    __shared__ int sh[1024];
    int i = blockIdx.x * 1024 + threadIdx.x;
    int v = (i < n) ? g_cnt[i] : 0;
    sh[threadIdx.x] = v;
    __syncthreads();
#pragma unroll
    for (int off = 1; off < 1024; off <<= 1) {
        int t = (threadIdx.x >= off) ? sh[threadIdx.x - off] : 0;
        __syncthreads();
        sh[threadIdx.x] += t;
        __syncthreads();
    }
    if (i < n) g_tmp[i] = sh[threadIdx.x];
    if (threadIdx.x == 1023) g_bsum[blockIdx.x] = sh[1023];
}

__global__ void k_scan2(int nb) { // one block, 128 threads
    int t = threadIdx.x;
    int orig = (t < nb) ? g_bsum[t] : 0;
    int v = orig;
#pragma unroll
    for (int off = 1; off < 32; off <<= 1) {
        int u = __shfl_up_sync(0xFFFFFFFF, v, off);
        if ((t & 31) >= off) v += u;
    }
    __shared__ int ws[4];
    if ((t & 31) == 31) ws[t >> 5] = v;
    __syncthreads();
    int add = 0;
    for (int w = 0; w < (t >> 5); w++) add += ws[w];
    v += add;
    if (t < nb) g_bpre[t] = v - orig; // exclusive
}

__global__ void k_scan3(int n) {
    int i = blockIdx.x * 1024 + threadIdx.x;
    if (i < n) {
        int inc = g_tmp[i] + g_bpre[blockIdx.x];
        g_off[i + 1] = inc;
        g_cur[i]     = inc - g_cnt[i];
    }
    if (i == 0) g_off[0] = 0;
}

__global__ void k_bucket(const int* __restrict__ src, const int* __restrict__ dst, int e) {
    int i = blockIdx.x * blockDim.x + threadIdx.x;
    if (i < e) {
        int d   = dst[i];
        int pos = atomicAdd(&g_cur[d], 1);
        g_ecsr[pos] = src[i];
    }
}

// ---------------- 4x4 register-tiled fp32 GEMM (R2-proven) --------------------
// TANH=false: out = (A@W) * dinv[row];  TANH=true: out = tanh(A@W + bias)
template <int K, int C, bool TANH>
__global__ void gemm_kernel(const float* __restrict__ A,
                            const float* __restrict__ W,
                            const float* __restrict__ bias,
                            float* __restrict__ out0,
                            int n) {
    constexpr int BM  = 128;
    constexpr int TN  = 4;
    constexpr int NCG = C / TN;
    constexpr int NRG = 256 / NCG;
    constexpr int TM  = BM / NRG;
    constexpr int KC  = 32;

    __shared__ float Ash[BM * KC];
    __shared__ float Bsh[KC * C];

    int tid = threadIdx.x;
    int m0  = blockIdx.x * BM;
    int tc  = tid % NCG;
    int tr  = tid / NCG;

    float acc[TM][TN];
#pragma unroll
    for (int i = 0; i < TM; i++)
#pragma unroll
        for (int j = 0; j < TN; j++) acc[i][j] = 0.0f;

    for (int kc = 0; kc < K; kc += KC) {
        constexpr int AF4 = BM * KC / 4;
#pragma unroll
        for (int t = tid; t < AF4; t += 256) {
            int r  = t / (KC / 4);
            int c4 = t % (KC / 4);
            float4 v = make_float4(0.f, 0.f, 0.f, 0.f);
            int row = m0 + r;
            if (row < n)
                v = *reinterpret_cast<const float4*>(&A[(size_t)row * K + kc + c4 * 4]);
            *reinterpret_cast<float4*>(&Ash[r * KC + c4 * 4]) = v;
        }
        constexpr int BF4 = KC * C / 4;
#pragma unroll
        for (int t = tid; t < BF4; t += 256) {
            int r  = t / (C / 4);
            int c4 = t % (C / 4);
            *reinterpret_cast<float4*>(&Bsh[r * C + c4 * 4]) =
                *reinterpret_cast<const float4*>(&W[(size_t)(kc + r) * C + c4 * 4]);
        }
        __syncthreads();
#pragma unroll
        for (int k4 = 0; k4 < KC / 4; k4++) {
            float4 b0 = *reinterpret_cast<const float4*>(&Bsh[(k4 * 4 + 0) * C + tc * TN]);
            float4 b1 = *reinterpret_cast<const float4*>(&Bsh[(k4 * 4 + 1) * C + tc * TN]);
            float4 b2 = *reinterpret_cast<const float4*>(&Bsh[(k4 * 4 + 2) * C + tc * TN]);
            float4 b3 = *reinterpret_cast<const float4*>(&Bsh[(k4 * 4 + 3) * C + tc * TN]);
#pragma unroll
            for (int i = 0; i < TM; i++) {
                float4 a = *reinterpret_cast<const float4*>(&Ash[(tr * TM + i) * KC + k4 * 4]);
                acc[i][0] += a.x * b0.x + a.y * b1.x + a.z * b2.x + a.w * b3.x;
                acc[i][1] += a.x * b0.y + a.y * b1.y + a.z * b2.y + a.w * b3.y;
                acc[i][2] += a.x * b0.z + a.y * b1.z + a.z * b2.z + a.w * b3.z;
                acc[i][3] += a.x * b0.w + a.y * b1.w + a.z * b2.w + a.w * b3.w;
            }
        }
        __syncthreads();
    }

#pragma unroll
    for (int i = 0; i < TM; i++) {
        int row = m0 + tr * TM + i;
        if (row >= n) continue;
        size_t base = (size_t)row * C + tc * TN;
        if (TANH) {
            float4 o;
            o.x = tanhf(acc[i][0] + bias[tc * TN + 0]);
            o.y = tanhf(acc[i][1] + bias[tc * TN + 1]);
            o.z = tanhf(acc[i][2] + bias[tc * TN + 2]);
            o.w = tanhf(acc[i][3] + bias[tc * TN + 3]);
            *reinterpret_cast<float4*>(&out0[base]) = o;
        } else {
            float sc = g_dinv[row];
            float4 o = make_float4(acc[i][0] * sc, acc[i][1] * sc,
                                   acc[i][2] * sc, acc[i][3] * sc);
            *reinterpret_cast<float4*>(&out0[base]) = o;
        }
    }
}

// ---------------- CSR gather, 4-edge MLP unroll, dual accumulators ------------
__global__ void gather128(const float* __restrict__ hs, const float* __restrict__ b1,
                          float* __restrict__ out, int n) {
    int warp = (blockIdx.x * blockDim.x + threadIdx.x) >> 5;
    int lane = threadIdx.x & 31;
    if (warp >= n) return;
    const int node = warp;
    const float4* base = reinterpret_cast<const float4*>(hs); // row r -> base + r*32 + lane
    float4 a0 = __ldg(base + (size_t)node * 32 + lane);
    float4 a1 = make_float4(0.f, 0.f, 0.f, 0.f);
    int j = g_off[node], jend = g_off[node + 1];
    for (; j + 4 <= jend; j += 4) {
        int s0 = __ldg(&g_ecsr[j]);
        int s1 = __ldg(&g_ecsr[j + 1]);
        int s2 = __ldg(&g_ecsr[j + 2]);
        int s3 = __ldg(&g_ecsr[j + 3]);
        float4 v0 = __ldg(base + (size_t)s0 * 32 + lane);
        float4 v1 = __ldg(base + (size_t)s1 * 32 + lane);
        float4 v2 = __ldg(base + (size_t)s2 * 32 + lane);
        float4 v3 = __ldg(base + (size_t)s3 * 32 + lane);
        a0.x += v0.x + v1.x; a0.y += v0.y + v1.y;
        a0.z += v0.z + v1.z; a0.w += v0.w + v1.w;
        a1.x += v2.x + v3.x; a1.y += v2.y + v3.y;
        a1.z += v2.z + v3.z; a1.w += v2.w + v3.w;
    }
    for (; j < jend; j++) {
        int s0 = __ldg(&g_ecsr[j]);
        float4 v0 = __ldg(base + (size_t)s0 * 32 + lane);
        a0.x += v0.x; a0.y += v0.y; a0.z += v0.z; a0.w += v0.w;
    }
    float4 acc = make_float4(a0.x + a1.x, a0.y + a1.y, a0.z + a1.z, a0.w + a1.w);
    float dn = g_dinv[node];
    float4 bb = *reinterpret_cast<const float4*>(&b1[lane * 4]);
    float4 o = make_float4(fmaxf(acc.x * dn + bb.x, 0.f), fmaxf(acc.y * dn + bb.y, 0.f),
                           fmaxf(acc.z * dn + bb.z, 0.f), fmaxf(acc.w * dn + bb.w, 0.f));
    *reinterpret_cast<float4*>(&out[(size_t)node * 128 + lane * 4]) = o;
}

__global__ void gather64(const float* __restrict__ hs, const float* __restrict__ b2,
                         float* __restrict__ out, int n) {
    int warp = (blockIdx.x * blockDim.x + threadIdx.x) >> 5;
    int lane = threadIdx.x & 31;
    if (warp >= n) return;
    const int node = warp;
    const float2* base = reinterpret_cast<const float2*>(hs); // row r -> base + r*32 + lane
    float2 a0 = __ldg(base + (size_t)node * 32 + lane);
    float2 a1 = make_float2(0.f, 0.f);
    int j = g_off[node], jend = g_off[node + 1];
    for (; j + 4 <= jend; j += 4) {
        int s0 = __ldg(&g_ecsr[j]);
        int s1 = __ldg(&g_ecsr[j + 1]);
        int s2 = __ldg(&g_ecsr[j + 2]);
        int s3 = __ldg(&g_ecsr[j + 3]);
        float2 v0 = __ldg(base + (size_t)s0 * 32 + lane);
        float2 v1 = __ldg(base + (size_t)s1 * 32 + lane);
        float2 v2 = __ldg(base + (size_t)s2 * 32 + lane);
        float2 v3 = __ldg(base + (size_t)s3 * 32 + lane);
        a0.x += v0.x + v1.x; a0.y += v0.y + v1.y;
        a1.x += v2.x + v3.x; a1.y += v2.y + v3.y;
    }
    for (; j < jend; j++) {
        int s0 = __ldg(&g_ecsr[j]);
        float2 v0 = __ldg(base + (size_t)s0 * 32 + lane);
        a0.x += v0.x; a0.y += v0.y;
    }
    float2 acc = make_float2(a0.x + a1.x, a0.y + a1.y);
    float dn = g_dinv[node];
    float2 bb = *reinterpret_cast<const float2*>(&b2[lane * 2]);
    float2 o = make_float2(acc.x * dn + bb.x, acc.y * dn + bb.y);
    *reinterpret_cast<float2*>(&out[(size_t)node * 64 + lane * 2]) = o;
}

// ---------------- attention logits -> exp(s), fused Z accumulation ------------
__global__ void k_logits(const float* __restrict__ a1, const float* __restrict__ Wf2,
                         const float* __restrict__ bf2, int n) {
    __shared__ float Wsh[64 * 8];
    __shared__ float bsh[8];
    __shared__ float red[256];
    int tid = threadIdx.x;
    for (int t = tid; t < 512; t += 256) Wsh[t] = Wf2[t];
    if (tid < 8) bsh[tid] = bf2[tid];
    __syncthreads();

    int node = blockIdx.x * 32 + (tid >> 3);
    int d    = tid & 7;
    float e  = 0.0f;
    if (node < n) {
        float acc = bsh[d];
        const float* ar = a1 + (size_t)node * 64;
#pragma unroll 8
        for (int j = 0; j < 64; j++) acc += ar[j] * Wsh[j * 8 + d];
        e = expf(acc);
        g_s[(size_t)node * 8 + d] = e;
    }
    red[tid] = e;
    __syncthreads();
    for (int off = 128; off >= 8; off >>= 1) {
        if (tid < off) red[tid] += red[tid + off];
        __syncthreads();
    }
    if (tid < 8) atomicAdd(&g_Z[tid], red[tid]);
}

// ---------------- pooled reductions: G = e.T@h2, C = e.T@e --------------------
__global__ void k_accum(int n) {
    __shared__ float h2sh[64 * 64];
    __shared__ float esh[64 * 8];
    int tid = threadIdx.x;
    int c0  = blockIdx.x * 64;
    int nv  = n - c0;
    if (nv > 64) nv = 64;

    for (int t = tid; t < 64 * 64; t += 256) {
        int row = t >> 6;
        if (row < nv) h2sh[t] = g_h2[(size_t)(c0 + row) * 64 + (t & 63)];
    }
    for (int t = tid; t < 512; t += 256) {
        int row = t >> 3;
        if (row < nv) esh[t] = g_s[(size_t)(c0 + row) * 8 + (t & 7)];
    }
    __syncthreads();

    int p0 = tid, p1 = tid + 256;
    int d0 = p0 >> 6, h0 = p0 & 63;
    int d1 = p1 >> 6, h1 = p1 & 63;
    int cd1 = tid >> 3, cd2 = tid & 7;
    float aG0 = 0.f, aG1 = 0.f, aC = 0.f;
    for (int m = 0; m < nv; m++) {
        float* hrow = &h2sh[m * 64];
        float* erow = &esh[m * 8];
        aG0 += erow[d0] * hrow[h0];
        aG1 += erow[d1] * hrow[h1];
        if (tid < 64) aC += erow[cd1] * erow[cd2];
    }
    atomicAdd(&g_G[p0], aG0);
    atomicAdd(&g_G[p1], aG1);
    if (tid < 64) atomicAdd(&g_C[tid], aC);
}

// ---------------- final: normalize, penalty, dense head, log_softmax ----------
__global__ void k_final(const float* __restrict__ Wl, const float* __restrict__ bl,
                        float* __restrict__ out) {
    __shared__ float ge[512];
    __shared__ float Zs[8];
    __shared__ float tmp[16];
    __shared__ float lg[10];
    int tid = threadIdx.x; // 64 threads
    if (tid < 8) Zs[tid] = g_Z[tid];
    __syncthreads();
    for (int p = tid; p < 512; p += 64) {
        float v = g_G[p] / Zs[p >> 6];
        ge[p]  = v;
        out[p] = v;
    }
    __syncthreads();
    if (tid < 8) {
        float ss = 0.f;
        for (int d2 = 0; d2 < 8; d2++) {
            float c = g_C[tid * 8 + d2] / (Zs[tid] * Zs[d2]) - (tid == d2 ? 1.0f : 0.0f);
            ss += c * c;
        }
        tmp[tid] = sqrtf(ss);
    }
    __syncthreads();
    if (tid == 0) {
        float pen = 0.f;
        for (int d = 0; d < 8; d++) pen += tmp[d];
        out[512] = pen;
    }
    if (tid < 10) {
        float acc = bl[tid];
        for (int p = 0; p < 512; p++) acc += ge[p] * Wl[p * 10 + tid];
        lg[tid] = acc;
    }
    __syncthreads();
    if (tid == 0) {
        float m = lg[0];
        for (int l = 1; l < 10; l++) m = fmaxf(m, lg[l]);
        float s = 0.f;
        for (int l = 0; l < 10; l++) s += expf(lg[l] - m);
        tmp[0] = m + logf(s);
    }
    __syncthreads();
    if (tid < 10) out[513 + tid] = lg[tid] - tmp[0];
}

// ---------------- launch -------------------------------------------------------
extern "C" void kernel_launch(void* const* d_in, const int* in_sizes, int n_in,
                              void* d_out, int out_size) {
    const int*   edges = (const int*)d_in[0];
    const float* X     = (const float*)d_in[1];
    const float* W1    = (const float*)d_in[2];
    const float* b1    = (const float*)d_in[3];
    const float* W2    = (const float*)d_in[4];
    const float* b2    = (const float*)d_in[5];
    const float* Wf1   = (const float*)d_in[6];
    const float* bf1   = (const float*)d_in[7];
    const float* Wf2   = (const float*)d_in[8];
    const float* bf2   = (const float*)d_in[9];
    const float* Wl    = (const float*)d_in[10];
    const float* bl    = (const float*)d_in[11];
    float* out = (float*)d_out;

    int e = in_sizes[0] / 2;
    int n = in_sizes[1] / 128;
    const int* src = edges;
    const int* dst = edges + e;

    float *pHs1, *pH1, *pH2s, *pH2;
    cudaGetSymbolAddress((void**)&pHs1, g_hs1);
    cudaGetSymbolAddress((void**)&pH1,  g_h1);
    cudaGetSymbolAddress((void**)&pH2s, g_h2s);
    cudaGetSymbolAddress((void**)&pH2,  g_h2);
    float* pA1 = pH1; // reuse h1 buffer for a1 (h1 dead after gemm2)

    const int T  = 256;
    const int NB = (n + 1023) / 1024;

    // CSR build + dinv (single stream)
    k_init  <<<(n + T - 1) / T, T>>>(n);
    k_deg   <<<(e + T - 1) / T, T>>>(dst, e);
    k_dinv  <<<(n + T - 1) / T, T>>>(n);
    k_scan1 <<<NB, 1024>>>(n);
    k_scan2 <<<1, 128>>>(NB);
    k_scan3 <<<NB, 1024>>>(n);
    k_bucket<<<(e + T - 1) / T, T>>>(src, dst, e);

    // layer 1: hs1 = (X@W1)*dinv; h1 = relu(gather(hs1)*dinv + b1)
    gemm_kernel<128, 128, false><<<(n + 127) / 128, T>>>(X, W1, nullptr, pHs1, n);
    gather128<<<(n + 7) / 8, T>>>(pHs1, b1, pH1, n);

    // layer 2: h2s = (h1@W2)*dinv; h2 = gather(h2s)*dinv + b2
    gemm_kernel<128, 64, false><<<(n + 127) / 128, T>>>(pH1, W2, nullptr, pH2s, n);
    gather64<<<(n + 7) / 8, T>>>(pH2s, b2, pH2, n);

    // attention
    gemm_kernel<64, 64, true><<<(n + 127) / 128, T>>>(pH2, Wf1, bf1, pA1, n);
    k_logits<<<(n + 31) / 32, T>>>(pA1, Wf2, bf2, n);
    k_accum <<<(n + 63) / 64, T>>>(n);

    // head
    k_final<<<1, 64>>>(Wl, bl, out);
}

// round 8
// speedup vs baseline: 1.2237x; 1.0869x over previous
#include <cuda_runtime.h>
#include <cuda_bf16.h>
#include <math.h>

#define MAXN 100000
#define MAXE 3200000

// ---------------- scratch (static device globals; no allocation) -------------
__device__ __nv_bfloat16 g_hs1[(size_t)MAXN * 128]; // (X@W1)*dinv, bf16 payload
__device__ float g_h1 [(size_t)MAXN * 128];         // h1; reused as a1 after gemm2
__device__ __nv_bfloat16 g_h2s[(size_t)MAXN * 64];  // (h1@W2)*dinv, bf16 payload
__device__ float g_h2 [(size_t)MAXN * 64];          // h2
__device__ float g_s  [(size_t)MAXN * 8];           // exp(attention logits)
__device__ float g_dinv[MAXN];
__device__ int   g_cnt [MAXN];
__device__ int   g_tmp [MAXN];
__device__ int   g_off [MAXN + 1];
__device__ int   g_cur [MAXN];
__device__ int   g_ecsr[MAXE];
__device__ int   g_bsum[128];
__device__ int   g_bpre[128];
__device__ float g_Z[8];
__device__ float g_G[512];
__device__ float g_C[64];

// ---------------- bf16 unpack helpers (pure ALU, no cvt pipe) -----------------
__device__ __forceinline__ float bf_lo(unsigned p) { return __uint_as_float(p << 16); }
__device__ __forceinline__ float bf_hi(unsigned p) { return __uint_as_float(p & 0xFFFF0000u); }

// ---------------- init / degree / CSR build ----------------------------------
__global__ void k_init(int n) {
    int i = blockIdx.x * blockDim.x + threadIdx.x;
    if (i < n)   g_cnt[i] = 0;
    if (i < 512) g_G[i] = 0.0f;
    if (i < 64)  g_C[i] = 0.0f;
    if (i < 8)   g_Z[i] = 0.0f;
}

__global__ void k_deg(const int* __restrict__ dst, int e) {
    int i = blockIdx.x * blockDim.x + threadIdx.x;
    if (i < e) atomicAdd(&g_cnt[dst[i]], 1);
}

__global__ void k_scan1(int n) {
    __shared__ int sh[1024];
    int i = blockIdx.x * 1024 + threadIdx.x;
    int v = (i < n) ? g_cnt[i] : 0;
    if (i < n) g_dinv[i] = rsqrtf((float)(v + 1)); // +1 self loop
    sh[threadIdx.x] = v;
    __syncthreads();
#pragma unroll
    for (int off = 1; off < 1024; off <<= 1) {
        int t = (threadIdx.x >= off) ? sh[threadIdx.x - off] : 0;
        __syncthreads();
        sh[threadIdx.x] += t;
        __syncthreads();
    }
    if (i < n) g_tmp[i] = sh[threadIdx.x];
    if (threadIdx.x == 1023) g_bsum[blockIdx.x] = sh[1023];
}

__global__ void k_scan2(int nb) { // one block, 128 threads
    int t = threadIdx.x;
    int orig = (t < nb) ? g_bsum[t] : 0;
    int v = orig;
#pragma unroll
    for (int off = 1; off < 32; off <<= 1) {
        int u = __shfl_up_sync(0xFFFFFFFF, v, off);
        if ((t & 31) >= off) v += u;
    }
    __shared__ int ws[4];
    if ((t & 31) == 31) ws[t >> 5] = v;
    __syncthreads();
    int add = 0;
    for (int w = 0; w < (t >> 5); w++) add += ws[w];
    v += add;
    if (t < nb) g_bpre[t] = v - orig; // exclusive
}

__global__ void k_scan3(int n) {
    int i = blockIdx.x * 1024 + threadIdx.x;
    if (i < n) {
        int inc = g_tmp[i] + g_bpre[blockIdx.x];
        g_off[i + 1] = inc;
        g_cur[i]     = inc - g_cnt[i];
    }
    if (i == 0) g_off[0] = 0;
}

__global__ void k_bucket(const int* __restrict__ src, const int* __restrict__ dst, int e) {
    int i = blockIdx.x * blockDim.x + threadIdx.x;
    if (i < e) {
        int d   = dst[i];
        int pos = atomicAdd(&g_cur[d], 1);
        g_ecsr[pos] = src[i];
    }
}

// ---------------- 4x4 register-tiled fp32 GEMM (R2-proven) --------------------
// MODE 0: out_bf16 = (A@W)*dinv[row];  MODE 1: out_f32 = tanh(A@W + bias)
template <int K, int C, int MODE>
__global__ void gemm_kernel(const float* __restrict__ A,
                            const float* __restrict__ W,
                            const float* __restrict__ bias,
                            __nv_bfloat16* __restrict__ outb,
                            float* __restrict__ outf,
                            int n) {
    constexpr int BM  = 128;
    constexpr int TN  = 4;
    constexpr int NCG = C / TN;
    constexpr int NRG = 256 / NCG;
    constexpr int TM  = BM / NRG;
    constexpr int KC  = 32;

    __shared__ float Ash[BM * KC];
    __shared__ float Bsh[KC * C];

    int tid = threadIdx.x;
    int m0  = blockIdx.x * BM;
    int tc  = tid % NCG;
    int tr  = tid / NCG;

    float acc[TM][TN];
#pragma unroll
    for (int i = 0; i < TM; i++)
#pragma unroll
        for (int j = 0; j < TN; j++) acc[i][j] = 0.0f;

    for (int kc = 0; kc < K; kc += KC) {
        constexpr int AF4 = BM * KC / 4;
#pragma unroll
        for (int t = tid; t < AF4; t += 256) {
            int r  = t / (KC / 4);
            int c4 = t % (KC / 4);
            float4 v = make_float4(0.f, 0.f, 0.f, 0.f);
            int row = m0 + r;
            if (row < n)
                v = *reinterpret_cast<const float4*>(&A[(size_t)row * K + kc + c4 * 4]);
            *reinterpret_cast<float4*>(&Ash[r * KC + c4 * 4]) = v;
        }
        constexpr int BF4 = KC * C / 4;
#pragma unroll
        for (int t = tid; t < BF4; t += 256) {
            int r  = t / (C / 4);
            int c4 = t % (C / 4);
            *reinterpret_cast<float4*>(&Bsh[r * C + c4 * 4]) =
                *reinterpret_cast<const float4*>(&W[(size_t)(kc + r) * C + c4 * 4]);
        }
        __syncthreads();
#pragma unroll
        for (int k4 = 0; k4 < KC / 4; k4++) {
            float4 b0 = *reinterpret_cast<const float4*>(&Bsh[(k4 * 4 + 0) * C + tc * TN]);
            float4 b1 = *reinterpret_cast<const float4*>(&Bsh[(k4 * 4 + 1) * C + tc * TN]);
            float4 b2 = *reinterpret_cast<const float4*>(&Bsh[(k4 * 4 + 2) * C + tc * TN]);
            float4 b3 = *reinterpret_cast<const float4*>(&Bsh[(k4 * 4 + 3) * C + tc * TN]);
#pragma unroll
            for (int i = 0; i < TM; i++) {
                float4 a = *reinterpret_cast<const float4*>(&Ash[(tr * TM + i) * KC + k4 * 4]);
                acc[i][0] += a.x * b0.x + a.y * b1.x + a.z * b2.x + a.w * b3.x;
                acc[i][1] += a.x * b0.y + a.y * b1.y + a.z * b2.y + a.w * b3.y;
                acc[i][2] += a.x * b0.z + a.y * b1.z + a.z * b2.z + a.w * b3.z;
                acc[i][3] += a.x * b0.w + a.y * b1.w + a.z * b2.w + a.w * b3.w;
            }
        }
        __syncthreads();
    }

#pragma unroll
    for (int i = 0; i < TM; i++) {
        int row = m0 + tr * TM + i;
        if (row >= n) continue;
        if (MODE == 0) {
            float sc = g_dinv[row];
            __nv_bfloat162 lo = __floats2bfloat162_rn(acc[i][0] * sc, acc[i][1] * sc);
            __nv_bfloat162 hi = __floats2bfloat162_rn(acc[i][2] * sc, acc[i][3] * sc);
            uint2 pk = make_uint2(*reinterpret_cast<unsigned*>(&lo),
                                  *reinterpret_cast<unsigned*>(&hi));
            *reinterpret_cast<uint2*>(&outb[(size_t)row * C + tc * TN]) = pk;
        } else {
            float4 o;
            o.x = tanhf(acc[i][0] + bias[tc * TN + 0]);
            o.y = tanhf(acc[i][1] + bias[tc * TN + 1]);
            o.z = tanhf(acc[i][2] + bias[tc * TN + 2]);
            o.w = tanhf(acc[i][3] + bias[tc * TN + 3]);
            *reinterpret_cast<float4*>(&outf[(size_t)row * C + tc * TN]) = o;
        }
    }
}

// ---------------- CSR gather, bf16 payload, shift unpack, unroll-4 -------------
// uint2 at (row*32 + lane) holds features {4*lane .. 4*lane+3} (contiguous)
__global__ void gather128(const __nv_bfloat16* __restrict__ hs,
                          const float* __restrict__ b1,
                          float* __restrict__ out, int n) {
    int warp = (blockIdx.x * blockDim.x + threadIdx.x) >> 5;
    int lane = threadIdx.x & 31;
    if (warp >= n) return;
    const int node = warp;
    const uint2* base = reinterpret_cast<const uint2*>(hs);
    uint2 ps = __ldg(base + (size_t)node * 32 + lane);
    float4 a0 = make_float4(bf_lo(ps.x), bf_hi(ps.x), bf_lo(ps.y), bf_hi(ps.y));
    float4 a1 = make_float4(0.f, 0.f, 0.f, 0.f);
    int j = g_off[node], jend = g_off[node + 1];
    for (; j + 4 <= jend; j += 4) {
        int s0 = __ldg(&g_ecsr[j]);
        int s1 = __ldg(&g_ecsr[j + 1]);
        int s2 = __ldg(&g_ecsr[j + 2]);
        int s3 = __ldg(&g_ecsr[j + 3]);
        uint2 p0 = __ldg(base + (size_t)s0 * 32 + lane);
        uint2 p1 = __ldg(base + (size_t)s1 * 32 + lane);
        uint2 p2 = __ldg(base + (size_t)s2 * 32 + lane);
        uint2 p3 = __ldg(base + (size_t)s3 * 32 + lane);
        a0.x += bf_lo(p0.x) + bf_lo(p1.x); a0.y += bf_hi(p0.x) + bf_hi(p1.x);
        a0.z += bf_lo(p0.y) + bf_lo(p1.y); a0.w += bf_hi(p0.y) + bf_hi(p1.y);
        a1.x += bf_lo(p2.x) + bf_lo(p3.x); a1.y += bf_hi(p2.x) + bf_hi(p3.x);
        a1.z += bf_lo(p2.y) + bf_lo(p3.y); a1.w += bf_hi(p2.y) + bf_hi(p3.y);
    }
    for (; j < jend; j++) {
        int s0 = __ldg(&g_ecsr[j]);
        uint2 p0 = __ldg(base + (size_t)s0 * 32 + lane);
        a0.x += bf_lo(p0.x); a0.y += bf_hi(p0.x);
        a0.z += bf_lo(p0.y); a0.w += bf_hi(p0.y);
    }
    float4 acc = make_float4(a0.x + a1.x, a0.y + a1.y, a0.z + a1.z, a0.w + a1.w);
    float dn = g_dinv[node];
    float4 bb = *reinterpret_cast<const float4*>(&b1[lane * 4]);
    float4 o = make_float4(fmaxf(acc.x * dn + bb.x, 0.f), fmaxf(acc.y * dn + bb.y, 0.f),
                           fmaxf(acc.z * dn + bb.z, 0.f), fmaxf(acc.w * dn + bb.w, 0.f));
    *reinterpret_cast<float4*>(&out[(size_t)node * 128 + lane * 4]) = o;
}

// unsigned at (row*32 + lane) holds features {2*lane, 2*lane+1}
__global__ void gather64(const __nv_bfloat16* __restrict__ hs,
                         const float* __restrict__ b2,
                         float* __restrict__ out, int n) {
    int warp = (blockIdx.x * blockDim.x + threadIdx.x) >> 5;
    int lane = threadIdx.x & 31;
    if (warp >= n) return;
    const int node = warp;
    const unsigned* base = reinterpret_cast<const unsigned*>(hs);
    unsigned ps = __ldg(base + (size_t)node * 32 + lane);
    float2 a0 = make_float2(bf_lo(ps), bf_hi(ps));
    float2 a1 = make_float2(0.f, 0.f);
    int j = g_off[node], jend = g_off[node + 1];
    for (; j + 4 <= jend; j += 4) {
        int s0 = __ldg(&g_ecsr[j]);
        int s1 = __ldg(&g_ecsr[j + 1]);
        int s2 = __ldg(&g_ecsr[j + 2]);
        int s3 = __ldg(&g_ecsr[j + 3]);
        unsigned p0 = __ldg(base + (size_t)s0 * 32 + lane);
        unsigned p1 = __ldg(base + (size_t)s1 * 32 + lane);
        unsigned p2 = __ldg(base + (size_t)s2 * 32 + lane);
        unsigned p3 = __ldg(base + (size_t)s3 * 32 + lane);
        a0.x += bf_lo(p0) + bf_lo(p1); a0.y += bf_hi(p0) + bf_hi(p1);
        a1.x += bf_lo(p2) + bf_lo(p3); a1.y += bf_hi(p2) + bf_hi(p3);
    }
    for (; j < jend; j++) {
        int s0 = __ldg(&g_ecsr[j]);
        unsigned p0 = __ldg(base + (size_t)s0 * 32 + lane);
        a0.x += bf_lo(p0); a0.y += bf_hi(p0);
    }
    float2 acc = make_float2(a0.x + a1.x, a0.y + a1.y);
    float dn = g_dinv[node];
    float2 bb = *reinterpret_cast<const float2*>(&b2[2 * lane]);
    float2 o = make_float2(acc.x * dn + bb.x, acc.y * dn + bb.y);
    *reinterpret_cast<float2*>(&out[(size_t)node * 64 + 2 * lane]) = o;
}

// ---------------- attention logits -> exp(s), fused Z accumulation ------------
__global__ void k_logits(const float* __restrict__ a1, const float* __restrict__ Wf2,
                         const float* __restrict__ bf2, int n) {
    __shared__ float Wsh[64 * 8];
    __shared__ float bsh[8];
    __shared__ float red[256];
    int tid = threadIdx.x;
    for (int t = tid; t < 512; t += 256) Wsh[t] = Wf2[t];
    if (tid < 8) bsh[tid] = bf2[tid];
    __syncthreads();

    int node = blockIdx.x * 32 + (tid >> 3);
    int d    = tid & 7;
    float e  = 0.0f;
    if (node < n) {
        float acc = bsh[d];
        const float* ar = a1 + (size_t)node * 64;
#pragma unroll 8
        for (int j = 0; j < 64; j++) acc += ar[j] * Wsh[j * 8 + d];
        e = expf(acc);
        g_s[(size_t)node * 8 + d] = e;
    }
    red[tid] = e;
    __syncthreads();
    for (int off = 128; off >= 8; off >>= 1) {
        if (tid < off) red[tid] += red[tid + off];
        __syncthreads();
    }
    if (tid < 8) atomicAdd(&g_Z[tid], red[tid]);
}

// ---------------- pooled reductions: G = e.T@h2, C = e.T@e --------------------
__global__ void k_accum(int n) {
    __shared__ float h2sh[64 * 64];
    __shared__ float esh[64 * 8];
    int tid = threadIdx.x;
    int c0  = blockIdx.x * 64;
    int nv  = n - c0;
    if (nv > 64) nv = 64;

    for (int t = tid; t < 64 * 64; t += 256) {
        int row = t >> 6;
        if (row < nv) h2sh[t] = g_h2[(size_t)(c0 + row) * 64 + (t & 63)];
    }
    for (int t = tid; t < 512; t += 256) {
        int row = t >> 3;
        if (row < nv) esh[t] = g_s[(size_t)(c0 + row) * 8 + (t & 7)];
    }
    __syncthreads();

    int p0 = tid, p1 = tid + 256;
    int d0 = p0 >> 6, h0 = p0 & 63;
    int d1 = p1 >> 6, h1 = p1 & 63;
    int cd1 = tid >> 3, cd2 = tid & 7;
    float aG0 = 0.f, aG1 = 0.f, aC = 0.f;
    for (int m = 0; m < nv; m++) {
        float* hrow = &h2sh[m * 64];
        float* erow = &esh[m * 8];
        aG0 += erow[d0] * hrow[h0];
        aG1 += erow[d1] * hrow[h1];
        if (tid < 64) aC += erow[cd1] * erow[cd2];
    }
    atomicAdd(&g_G[p0], aG0);
    atomicAdd(&g_G[p1], aG1);
    if (tid < 64) atomicAdd(&g_C[tid], aC);
}

// ---------------- final: normalize, penalty, dense head, log_softmax ----------
__global__ void k_final(const float* __restrict__ Wl, const float* __restrict__ bl,
                        float* __restrict__ out) {
    __shared__ float ge[512];
    __shared__ float Zs[8];
    __shared__ float tmp[16];
    __shared__ float lg[10];
    int tid = threadIdx.x; // 64 threads
    if (tid < 8) Zs[tid] = g_Z[tid];
    __syncthreads();
    for (int p = tid; p < 512; p += 64) {
        float v = g_G[p] / Zs[p >> 6];
        ge[p]  = v;
        out[p] = v;
    }
    __syncthreads();
    if (tid < 8) {
        float ss = 0.f;
        for (int d2 = 0; d2 < 8; d2++) {
            float c = g_C[tid * 8 + d2] / (Zs[tid] * Zs[d2]) - (tid == d2 ? 1.0f : 0.0f);
            ss += c * c;
        }
        tmp[tid] = sqrtf(ss);
    }
    __syncthreads();
    if (tid == 0) {
        float pen = 0.f;
        for (int d = 0; d < 8; d++) pen += tmp[d];
        out[512] = pen;
    }
    if (tid < 10) {
        float acc = bl[tid];
        for (int p = 0; p < 512; p++) acc += ge[p] * Wl[p * 10 + tid];
        lg[tid] = acc;
    }
    __syncthreads();
    if (tid == 0) {
        float m = lg[0];
        for (int l = 1; l < 10; l++) m = fmaxf(m, lg[l]);
        float s = 0.f;
        for (int l = 0; l < 10; l++) s += expf(lg[l] - m);
        tmp[0] = m + logf(s);
    }
    __syncthreads();
    if (tid < 10) out[513 + tid] = lg[tid] - tmp[0];
}

// ---------------- launch -------------------------------------------------------
extern "C" void kernel_launch(void* const* d_in, const int* in_sizes, int n_in,
                              void* d_out, int out_size) {
    const int*   edges = (const int*)d_in[0];
    const float* X     = (const float*)d_in[1];
    const float* W1    = (const float*)d_in[2];
    const float* b1    = (const float*)d_in[3];
    const float* W2    = (const float*)d_in[4];
    const float* b2    = (const float*)d_in[5];
    const float* Wf1   = (const float*)d_in[6];
    const float* bf1   = (const float*)d_in[7];
    const float* Wf2   = (const float*)d_in[8];
    const float* bf2   = (const float*)d_in[9];
    const float* Wl    = (const float*)d_in[10];
    const float* bl    = (const float*)d_in[11];
    float* out = (float*)d_out;

    int e = in_sizes[0] / 2;
    int n = in_sizes[1] / 128;
    const int* src = edges;
    const int* dst = edges + e;

    __nv_bfloat16 *pHs1, *pH2s;
    float *pH1, *pH2;
    cudaGetSymbolAddress((void**)&pHs1, g_hs1);
    cudaGetSymbolAddress((void**)&pH1,  g_h1);
    cudaGetSymbolAddress((void**)&pH2s, g_h2s);
    cudaGetSymbolAddress((void**)&pH2,  g_h2);
    float* pA1 = pH1; // reuse h1 buffer for a1 (h1 dead after gemm2)

    const int T  = 256;
    const int NB = (n + 1023) / 1024;

    // CSR build + dinv (single stream)
    k_init  <<<(n + T - 1) / T, T>>>(n);
    k_deg   <<<(e + T - 1) / T, T>>>(dst, e);
    k_scan1 <<<NB, 1024>>>(n);
    k_scan2 <<<1, 128>>>(NB);
    k_scan3 <<<NB, 1024>>>(n);
    k_bucket<<<(e + T - 1) / T, T>>>(src, dst, e);

    // layer 1: hs1 = (X@W1)*dinv (bf16); h1 = relu(gather(hs1)*dinv + b1)
    gemm_kernel<128, 128, 0><<<(n + 127) / 128, T>>>(X, W1, nullptr, pHs1, nullptr, n);
    gather128<<<(n + 7) / 8, T>>>(pHs1, b1, pH1, n);

    // layer 2: h2s = (h1@W2)*dinv (bf16); h2 = gather(h2s)*dinv + b2
    gemm_kernel<128, 64, 0><<<(n + 127) / 128, T>>>(pH1, W2, nullptr, pH2s, nullptr, n);
    gather64<<<(n + 7) / 8, T>>>(pH2s, b2, pH2, n);

    // attention
    gemm_kernel<64, 64, 1><<<(n + 127) / 128, T>>>(pH2, Wf1, bf1, nullptr, pA1, n);
    k_logits<<<(n + 31) / 32, T>>>(pA1, Wf2, bf2, n);
    k_accum <<<(n + 63) / 64, T>>>(n);

    // head
    k_final<<<1, 64>>>(Wl, bl, out);
}